// round 5
// baseline (speedup 1.0000x reference)
#include <cuda_runtime.h>

// Dense_RBS_density_3D: rho_out = W rho W^T, W = 39 sparse Givens layers
// (38 disjoint 2x2 column rotations each) on the C(40,2)=780-dim basis.
// K(M) = (M W^T)^T = W M^T applied twice => W rho W^T. Two launches with a
// private __device__ scratch between.
//
// R5 vs R4: (1) load phase uses scalar lane-stride-4B copies -> conflict-free
// STS (was 4-way conflicted, ~20% of block wavefronts); (2) 1024 threads
// (32 warps, occ 25%->50%) for latency hiding; rotate = 30 warps x 2 rows.

#define DD      780
#define NGATES  39
#define NPAIRS  38
#define NBATCH  64
#define RROWS   60            // rows per tile
#define NTILES  13            // 780 / 60
#define STRIDE  781           // odd -> conflict-free transposed smem reads
#define THREADS 1024
#define TILEF   (RROWS * DD)  // 46800 floats per tile (contiguous in gmem)
#define TILEF_FULL ((TILEF / THREADS) * THREADS)   // 46080

__device__ float g_tmp[(size_t)NBATCH * DD * DD];  // 155.7 MB scratch

__device__ __forceinline__ int pair_rank(int p, int q) {  // p<q, 40 qubits
    return p * 39 - (p * (p - 1)) / 2 + (q - p - 1);
}

__device__ __forceinline__ void rbs_body(const float* __restrict__ in,
                                         float* __restrict__ out,
                                         const float* __restrict__ angles) {
    extern __shared__ float tile[];                 // RROWS * STRIDE
    __shared__ float   s_cos[NGATES], s_sin[NGATES];
    __shared__ ushort2 s_off[NGATES * NPAIRS];      // byte offsets (i*4, j*4)

    const int tid = threadIdx.x;
    const int b   = blockIdx.x / NTILES;
    const int t   = blockIdx.x - b * NTILES;
    const int r0  = t * RROWS;

    if (tid < NGATES) {
        float th = angles[tid];
        s_cos[tid] = cosf(th);
        s_sin[tid] = sinf(th);
    }
    for (int n = tid; n < NGATES * NPAIRS; n += THREADS) {
        int g = n / NPAIRS;
        int p = n - g * NPAIRS;
        int x = p + (p >= g ? 2 : 0);                        // qubit != g,g+1
        int i = (x < g)     ? pair_rank(x, g)     : pair_rank(g, x);
        int j = (x < g + 1) ? pair_rank(x, g + 1) : pair_rank(g + 1, x);
        s_off[n] = make_ushort2((unsigned short)(i * 4), (unsigned short)(j * 4));
    }

    // ---------- load: rows [r0, r0+60) are CONTIGUOUS in gmem ------------
    // tile[n + n/780] = src[n]  (stride-781 remap). Lane stride 4B both
    // sides: coalesced LDG.32, conflict-free STS.32. Front-batched.
    {
        const float* src = in + (size_t)b * DD * DD + (size_t)r0 * DD;
        #pragma unroll 9
        for (int k = 0; k < TILEF_FULL / THREADS; k++) {     // 45 uniform iters
            int n = tid + k * THREADS;
            tile[n + n / DD] = __ldg(src + n);
        }
        int n = tid + TILEF_FULL;                            // tail: 720 threads
        if (n < TILEF) tile[n + n / DD] = __ldg(src + n);
    }
    __syncthreads();

    // ---------- rotate: warp-autonomous, 2 rows per warp, no block bar ---
    {
        const int w    = tid >> 5;
        const int lane = tid & 31;
        if (w < 30) {
            // items n = 2*pair + row_in_warp, n in [0,76); lane gets n, n+32, n+64
            char* rp[3]; int pidx[3]; bool act[3];
            #pragma unroll
            for (int k = 0; k < 3; k++) {
                int n   = 32 * k + lane;
                act[k]  = (n < NPAIRS * 2);                  // 76 items
                pidx[k] = n >> 1;
                rp[k]   = (char*)&tile[(2 * w + (n & 1)) * STRIDE];
            }
            #pragma unroll 1
            for (int g = 0; g < NGATES; g++) {
                const float cg = s_cos[g], sg = s_sin[g];
                const ushort2* go = &s_off[g * NPAIRS];
                #pragma unroll
                for (int k = 0; k < 3; k++) {
                    if (act[k]) {
                        ushort2 o = go[pidx[k]];
                        float* bi = (float*)(rp[k] + o.x);
                        float* bj = (float*)(rp[k] + o.y);
                        float xi = *bi, xj = *bj;
                        *bi = cg * xi - sg * xj;
                        *bj = sg * xi + cg * xj;
                    }
                }
                __syncwarp();
            }
        }
    }
    __syncthreads();

    // ---------- transposed store: out[b, col, r0+row], coalesced ----------
    {
        float* dstb = out + (size_t)b * DD * DD + r0;
        #pragma unroll 4
        for (int n = tid; n < TILEF; n += THREADS) {
            int col = n / RROWS;
            int row = n - col * RROWS;
            dstb[(size_t)col * DD + row] = tile[row * STRIDE + col];
        }
    }
}

__global__ __launch_bounds__(THREADS, 1)
void rbs_pass1(const float* __restrict__ in, const float* __restrict__ angles) {
    rbs_body(in, g_tmp, angles);
}

__global__ __launch_bounds__(THREADS, 1)
void rbs_pass2(float* __restrict__ out, const float* __restrict__ angles) {
    rbs_body(g_tmp, out, angles);
}

extern "C" void kernel_launch(void* const* d_in, const int* in_sizes, int n_in,
                              void* d_out, int out_size) {
    const float* input_state = (const float*)d_in[0];  // [64,780,780] f32
    const float* angles      = (const float*)d_in[1];  // [39] f32
    float* out = (float*)d_out;

    const int smem = RROWS * STRIDE * sizeof(float);   // 187,440 B
    cudaFuncSetAttribute(rbs_pass1, cudaFuncAttributeMaxDynamicSharedMemorySize, smem);
    cudaFuncSetAttribute(rbs_pass2, cudaFuncAttributeMaxDynamicSharedMemorySize, smem);

    dim3 grid(NBATCH * NTILES);   // 832 blocks
    rbs_pass1<<<grid, THREADS, smem>>>(input_state, angles);
    rbs_pass2<<<grid, THREADS, smem>>>(out, angles);
}

// round 6
// speedup vs baseline: 1.2548x; 1.2548x over previous
#include <cuda_runtime.h>

// Dense_RBS_density_3D: rho_out = W rho W^T, W = 39 sparse Givens layers
// (38 disjoint 2x2 column rotations each) on the C(40,2)=780-dim basis.
// K(M) = (M W^T)^T = W M^T applied twice => W rho W^T. Two launches with a
// private __device__ scratch between.
//
// R6 vs R4 (same geometry: 512 thr, 60-row stride-781 tiles, warp-autonomous
// rotate with 4 rows/warp):
//  (1) frontier-carry rotate: thread keeps pair-index x across gates; gate g's
//      rotated j-value {g+1,x} is gate g+1's i-input -> carried in a register.
//      1 LDS + 1 STS per item-gate instead of 2+2 (segment resume/flush at the
//      x-break). Halves rotate smem wavefronts.
//  (2) float2 load path: 2-way STS conflict instead of float4's 4-way.

#define DD      780
#define NGATES  39
#define NBATCH  64
#define RROWS   60            // rows per tile
#define NTILES  13            // 780 / 60
#define STRIDE  781           // odd -> conflict-free transposed smem reads
#define THREADS 512
#define TILE2   (RROWS * DD / 2)                 // 23400 float2 per tile
#define TILE2_FULL ((TILE2 / THREADS) * THREADS) // 23040

__device__ float g_tmp[(size_t)NBATCH * DD * DD];  // 155.7 MB scratch

__device__ __forceinline__ int pair_rank(int p, int q) {  // p<q, 40 qubits
    return p * 39 - (p * (p - 1)) / 2 + (q - p - 1);
}

__device__ __forceinline__ void rbs_body(const float* __restrict__ in,
                                         float* __restrict__ out,
                                         const float* __restrict__ angles) {
    extern __shared__ float tile[];                 // RROWS * STRIDE
    __shared__ float s_cos[NGATES], s_sin[NGATES];
    __shared__ unsigned int s_oij[NGATES * 40];     // oi*4 | (oj*4 << 16)

    const int tid = threadIdx.x;
    const int b   = blockIdx.x / NTILES;
    const int t   = blockIdx.x - b * NTILES;
    const int r0  = t * RROWS;

    if (tid < NGATES) {
        float th = angles[tid];
        s_cos[tid] = cosf(th);
        s_sin[tid] = sinf(th);
    }
    // offset table: for gate g and pair-index x (x != g, g+1):
    //   oi = 4*rank({g,x}), oj = 4*rank({g+1,x})
    for (int n = tid; n < NGATES * 40; n += THREADS) {
        int g = n / 40, x = n - 40 * g;
        unsigned int v = 0;
        if (x != g && x != g + 1) {
            int i = (x < g)     ? pair_rank(x, g)     : pair_rank(g, x);
            int j = (x < g + 1) ? pair_rank(x, g + 1) : pair_rank(g + 1, x);
            v = (unsigned int)(i * 4) | ((unsigned int)(j * 4) << 16);
        }
        s_oij[n] = v;
    }

    // ---------- load: rows [r0,r0+60) contiguous in gmem; float2 ----------
    {
        const float2* src2 = (const float2*)(in + (size_t)b * DD * DD
                                                + (size_t)r0 * DD);
        #pragma unroll 9
        for (int k = 0; k < TILE2_FULL / THREADS; k++) {     // 45 uniform iters
            int n   = tid + k * THREADS;
            int row = n / (DD / 2);
            int c2  = n - row * (DD / 2);
            float2 v = __ldg(src2 + n);
            float* d = &tile[row * STRIDE + 2 * c2];
            d[0] = v.x; d[1] = v.y;
        }
        int n = tid + TILE2_FULL;                            // tail: 360 threads
        if (n < TILE2) {
            int row = n / (DD / 2);
            int c2  = n - row * (DD / 2);
            float2 v = __ldg(src2 + n);
            float* d = &tile[row * STRIDE + 2 * c2];
            d[0] = v.x; d[1] = v.y;
        }
    }
    __syncthreads();

    // ---------- rotate: warp-autonomous, frontier-carry ----------
    {
        const int w    = tid >> 5;
        const int lane = tid & 31;
        if (w < 15) {
            // item n = 32k+lane in [0,160): x = n>>2 (0..39), row = n&3
            int   xk[5];
            char* rp[5];
            float carry[5];
            #pragma unroll
            for (int k = 0; k < 5; k++) {
                int n = 32 * k + lane;
                xk[k]    = n >> 2;
                rp[k]    = (char*)&tile[(4 * w + (n & 3)) * STRIDE];
                carry[k] = 0.0f;
            }
            #pragma unroll 1
            for (int g = 0; g < NGATES; g++) {
                const float cg = s_cos[g], sg = s_sin[g];
                const unsigned int* go = &s_oij[g * 40];
                #pragma unroll
                for (int k = 0; k < 5; k++) {
                    const int x = xk[k];
                    if (x != g && x != g + 1) {              // active this gate
                        unsigned int oij = go[x];
                        float* pi = (float*)(rp[k] + (oij & 0xFFFFu));
                        float* pj = (float*)(rp[k] + (oij >> 16));
                        float xj = *pj;
                        float xi = (g == 0 || g == x + 1) ? *pi : carry[k];
                        *pi = cg * xi - sg * xj;             // done: {g,x}
                        float nj = sg * xi + cg * xj;        // frontier {g+1,x}
                        carry[k] = nj;
                        if (g == x - 2 || g == NGATES - 1)   // segment end
                            *pj = nj;                        // flush frontier
                    }
                }
                __syncwarp();
            }
        }
    }
    __syncthreads();

    // ---------- transposed store: out[b, col, r0+row], coalesced ----------
    {
        float* dstb = out + (size_t)b * DD * DD + r0;
        #pragma unroll 4
        for (int n = tid; n < DD * RROWS; n += THREADS) {
            int col = n / RROWS;
            int row = n - col * RROWS;
            dstb[(size_t)col * DD + row] = tile[row * STRIDE + col];
        }
    }
}

__global__ __launch_bounds__(THREADS, 1)
void rbs_pass1(const float* __restrict__ in, const float* __restrict__ angles) {
    rbs_body(in, g_tmp, angles);
}

__global__ __launch_bounds__(THREADS, 1)
void rbs_pass2(float* __restrict__ out, const float* __restrict__ angles) {
    rbs_body(g_tmp, out, angles);
}

extern "C" void kernel_launch(void* const* d_in, const int* in_sizes, int n_in,
                              void* d_out, int out_size) {
    const float* input_state = (const float*)d_in[0];  // [64,780,780] f32
    const float* angles      = (const float*)d_in[1];  // [39] f32
    float* out = (float*)d_out;

    const int smem = RROWS * STRIDE * sizeof(float);   // 187,440 B dynamic
    cudaFuncSetAttribute(rbs_pass1, cudaFuncAttributeMaxDynamicSharedMemorySize, smem);
    cudaFuncSetAttribute(rbs_pass2, cudaFuncAttributeMaxDynamicSharedMemorySize, smem);

    dim3 grid(NBATCH * NTILES);   // 832 blocks
    rbs_pass1<<<grid, THREADS, smem>>>(input_state, angles);
    rbs_pass2<<<grid, THREADS, smem>>>(out, angles);
}

// round 7
// speedup vs baseline: 1.3945x; 1.1113x over previous
#include <cuda_runtime.h>

// Dense_RBS_density_3D: rho_out = W rho W^T, W = 39 sparse Givens layers
// (38 disjoint 2x2 column rotations each) on the C(40,2)=780-dim basis.
// K(M) = (M W^T)^T = W M^T applied twice => W rho W^T. Two launches with a
// private __device__ scratch between.
//
// R7 vs R6: ONLY change is tile 60->30 rows => 93.7 KB smem => 2 CTAs/SM
// (occ 25%->50%), so one CTA's gmem phases overlap the other's rotate phase.
// Rotate stays warp-autonomous frontier-carry (2 rows/warp now).

#define DD      780
#define NGATES  39
#define NBATCH  64
#define RROWS   30            // rows per tile
#define NTILES  26            // 780 / 30
#define STRIDE  781           // odd -> conflict-free transposed smem reads
#define THREADS 512
#define TILE2   (RROWS * DD / 2)                 // 11700 float2 per tile
#define TILE2_FULL ((TILE2 / THREADS) * THREADS) // 11264

__device__ float g_tmp[(size_t)NBATCH * DD * DD];  // 155.7 MB scratch

__device__ __forceinline__ int pair_rank(int p, int q) {  // p<q, 40 qubits
    return p * 39 - (p * (p - 1)) / 2 + (q - p - 1);
}

__device__ __forceinline__ void rbs_body(const float* __restrict__ in,
                                         float* __restrict__ out,
                                         const float* __restrict__ angles) {
    extern __shared__ float tile[];                 // RROWS * STRIDE
    __shared__ float s_cos[NGATES], s_sin[NGATES];
    __shared__ unsigned int s_oij[NGATES * 40];     // oi*4 | (oj*4 << 16)

    const int tid = threadIdx.x;
    const int b   = blockIdx.x / NTILES;
    const int t   = blockIdx.x - b * NTILES;
    const int r0  = t * RROWS;

    if (tid < NGATES) {
        float th = angles[tid];
        s_cos[tid] = cosf(th);
        s_sin[tid] = sinf(th);
    }
    // offset table: for gate g and pair-index x (x != g, g+1):
    //   oi = 4*rank({g,x}), oj = 4*rank({g+1,x})
    for (int n = tid; n < NGATES * 40; n += THREADS) {
        int g = n / 40, x = n - 40 * g;
        unsigned int v = 0;
        if (x != g && x != g + 1) {
            int i = (x < g)     ? pair_rank(x, g)     : pair_rank(g, x);
            int j = (x < g + 1) ? pair_rank(x, g + 1) : pair_rank(g + 1, x);
            v = (unsigned int)(i * 4) | ((unsigned int)(j * 4) << 16);
        }
        s_oij[n] = v;
    }

    // ---------- load: rows [r0,r0+30) contiguous in gmem; float2 ----------
    {
        const float2* src2 = (const float2*)(in + (size_t)b * DD * DD
                                                + (size_t)r0 * DD);
        #pragma unroll 11
        for (int k = 0; k < TILE2_FULL / THREADS; k++) {     // 22 uniform iters
            int n   = tid + k * THREADS;
            int row = n / (DD / 2);
            int c2  = n - row * (DD / 2);
            float2 v = __ldg(src2 + n);
            float* d = &tile[row * STRIDE + 2 * c2];
            d[0] = v.x; d[1] = v.y;
        }
        int n = tid + TILE2_FULL;                            // tail: 436 threads
        if (n < TILE2) {
            int row = n / (DD / 2);
            int c2  = n - row * (DD / 2);
            float2 v = __ldg(src2 + n);
            float* d = &tile[row * STRIDE + 2 * c2];
            d[0] = v.x; d[1] = v.y;
        }
    }
    __syncthreads();

    // ---------- rotate: warp-autonomous, frontier-carry, 2 rows/warp ------
    {
        const int w    = tid >> 5;
        const int lane = tid & 31;
        if (w < 15) {
            // item n = 32k+lane in [0,80): x = n>>1 (0..39), row = n&1
            int   xk[3];
            char* rp[3];
            bool  act[3];
            float carry[3];
            #pragma unroll
            for (int k = 0; k < 3; k++) {
                int n = 32 * k + lane;
                act[k]   = (n < 80);
                xk[k]    = n >> 1;
                rp[k]    = (char*)&tile[(2 * w + (n & 1)) * STRIDE];
                carry[k] = 0.0f;
            }
            #pragma unroll 1
            for (int g = 0; g < NGATES; g++) {
                const float cg = s_cos[g], sg = s_sin[g];
                const unsigned int* go = &s_oij[g * 40];
                #pragma unroll
                for (int k = 0; k < 3; k++) {
                    const int x = xk[k];
                    if (act[k] && x != g && x != g + 1) {    // active this gate
                        unsigned int oij = go[x];
                        float* pi = (float*)(rp[k] + (oij & 0xFFFFu));
                        float* pj = (float*)(rp[k] + (oij >> 16));
                        float xj = *pj;
                        float xi = (g == 0 || g == x + 1) ? *pi : carry[k];
                        *pi = cg * xi - sg * xj;             // done: {g,x}
                        float nj = sg * xi + cg * xj;        // frontier {g+1,x}
                        carry[k] = nj;
                        if (g == x - 2 || g == NGATES - 1)   // segment end
                            *pj = nj;                        // flush frontier
                    }
                }
                __syncwarp();
            }
        }
    }
    __syncthreads();

    // ---------- transposed store: out[b, col, r0+row], coalesced ----------
    {
        float* dstb = out + (size_t)b * DD * DD + r0;
        #pragma unroll 4
        for (int n = tid; n < DD * RROWS; n += THREADS) {
            int col = n / RROWS;
            int row = n - col * RROWS;
            dstb[(size_t)col * DD + row] = tile[row * STRIDE + col];
        }
    }
}

__global__ __launch_bounds__(THREADS, 2)
void rbs_pass1(const float* __restrict__ in, const float* __restrict__ angles) {
    rbs_body(in, g_tmp, angles);
}

__global__ __launch_bounds__(THREADS, 2)
void rbs_pass2(float* __restrict__ out, const float* __restrict__ angles) {
    rbs_body(g_tmp, out, angles);
}

extern "C" void kernel_launch(void* const* d_in, const int* in_sizes, int n_in,
                              void* d_out, int out_size) {
    const float* input_state = (const float*)d_in[0];  // [64,780,780] f32
    const float* angles      = (const float*)d_in[1];  // [39] f32
    float* out = (float*)d_out;

    const int smem = RROWS * STRIDE * sizeof(float);   // 93,720 B dynamic
    cudaFuncSetAttribute(rbs_pass1, cudaFuncAttributeMaxDynamicSharedMemorySize, smem);
    cudaFuncSetAttribute(rbs_pass2, cudaFuncAttributeMaxDynamicSharedMemorySize, smem);

    dim3 grid(NBATCH * NTILES);   // 1664 blocks
    rbs_pass1<<<grid, THREADS, smem>>>(input_state, angles);
    rbs_pass2<<<grid, THREADS, smem>>>(out, angles);
}